// round 1
// baseline (speedup 1.0000x reference)
#include <cuda_runtime.h>
#include <math.h>

// Problem constants
#define NB      8192      // batch
#define ND      32        // dims
#define NK      64        // mixture components
#define NSTEP   255       // Euler-Maruyama steps (N_ITER - 1)
#define TPB     256       // threads per block
#define SPB     64        // samples per block (TPB / 4)
#define GSIZE   4         // threads cooperating per sample (K split)
#define KPER    (NK / GSIZE)   // 16 components per thread
#define STRIDE  36        // smem row stride in floats (144B, 16B aligned, conflict-free)

__global__ __launch_bounds__(TPB, 1)
void sbm_kernel(const float* __restrict__ x_init,
                const float* __restrict__ centers,
                const float* __restrict__ stds,
                const float* __restrict__ weights,
                const float* __restrict__ noise,
                float* __restrict__ out)
{
    __shared__ float sm_m [NK * STRIDE];
    __shared__ float sm_iv[NK * STRIDE];
    __shared__ float sm_c [NK];

    const int tid    = threadIdx.x;
    const int kpart  = tid & (GSIZE - 1);
    const int sample = blockIdx.x * SPB + (tid >> 2);

    // table-build assignment: thread -> (component tk, dim octet td0)
    const int tk  = tid >> 2;            // 0..63
    const int td0 = (tid & 3) * 8;       // 0,8,16,24

    float x[ND];
    {
        const float4* xp = reinterpret_cast<const float4*>(x_init + (size_t)sample * ND);
        #pragma unroll
        for (int j = 0; j < 8; j++) {
            float4 v = xp[j];
            x[4*j+0] = v.x; x[4*j+1] = v.y; x[4*j+2] = v.z; x[4*j+3] = v.w;
        }
    }

    const float T_MAX = 1.0f;
    const float T_MIN = 1e-4f;
    const float H   = (T_MAX - T_MIN) / 255.0f;   // |dt| per step
    const float SQH = sqrtf(H);

    for (int i = 0; i < NSTEP; i++) {
        // schedule scalars (cheap, uniform across threads)
        float t  = T_MAX - (float)i * H;                 // times[i] of reversed linspace
        float bt = 0.1f + 19.9f * t;                     // beta(t)
        float Bt = 0.1f * t + 9.95f * t * t;             // Beta(t)
        float eB = expf(-Bt);
        float om = 1.0f - eB;                            // matches reference's 1 - exp(-B)
        float sq = sqrtf(eB);
        float hb = H * bt;                               // -dt * beta
        float sn = sqrtf(bt) * SQH;                      // sqrt(beta)*sqrt(|dt|)

        __syncthreads();   // previous step's table readers are done

        // ---- build per-step mixture table in smem ----
        {
            float lsum = 0.0f;
            #pragma unroll
            for (int j = 0; j < 8; j++) {
                int d     = td0 + j;
                float c   = centers[tk * ND + d];
                float sd  = stds   [tk * ND + d];
                float v   = eB * sd * sd + om;           // diffused variance
                sm_m [tk * STRIDE + d] = sq * c;         // diffused mean
                sm_iv[tk * STRIDE + d] = 1.0f / v;
                lsum += __logf(6.2831853071795864f * v);
            }
            lsum += __shfl_xor_sync(0xffffffffu, lsum, 1);
            lsum += __shfl_xor_sync(0xffffffffu, lsum, 2);
            if ((tid & 3) == 0) {
                // reference: -(0.5*D) * sum(log(2*pi*v)) + log(w)   with D = 32
                sm_c[tk] = fmaf(-16.0f, lsum, __logf(weights[tk]));
            }
        }
        __syncthreads();

        // ---- per-sample score: online softmax over this thread's 16 components ----
        float M = -INFINITY;
        float S = 0.0f;
        float acc[ND];
        float dv [ND];
        #pragma unroll
        for (int d = 0; d < ND; d++) acc[d] = 0.0f;

        for (int kk = 0; kk < KPER; kk++) {
            int k = kk * GSIZE + kpart;    // consecutive k across the 4-thread group
            const float4* mp4  = reinterpret_cast<const float4*>(sm_m  + k * STRIDE);
            const float4* ivp4 = reinterpret_cast<const float4*>(sm_iv + k * STRIDE);

            float s0 = 0.f, s1 = 0.f, s2 = 0.f, s3 = 0.f;
            #pragma unroll
            for (int j = 0; j < 8; j++) {
                float4 m  = mp4[j];
                float4 iv = ivp4[j];
                int d = 4 * j;
                float a0 = x[d+0] - m.x;
                float a1 = x[d+1] - m.y;
                float a2 = x[d+2] - m.z;
                float a3 = x[d+3] - m.w;
                float b0 = a0 * iv.x;
                float b1 = a1 * iv.y;
                float b2 = a2 * iv.z;
                float b3 = a3 * iv.w;
                s0 = fmaf(b0, a0, s0);
                s1 = fmaf(b1, a1, s1);
                s2 = fmaf(b2, a2, s2);
                s3 = fmaf(b3, a3, s3);
                dv[d+0] = b0; dv[d+1] = b1; dv[d+2] = b2; dv[d+3] = b3;
            }
            float logc = fmaf(-0.5f, (s0 + s1) + (s2 + s3), sm_c[k]);

            if (logc > M) {
                float r = __expf(M - logc);   // exp(-inf) = 0 handles first component
                S = fmaf(S, r, 1.0f);
                #pragma unroll
                for (int d = 0; d < ND; d++) acc[d] = fmaf(acc[d], r, dv[d]);
                M = logc;
            } else {
                float w = __expf(logc - M);
                S += w;
                #pragma unroll
                for (int d = 0; d < ND; d++) acc[d] = fmaf(w, dv[d], acc[d]);
            }
        }

        // ---- merge the 4 partial softmax states (xor 1, xor 2) ----
        #pragma unroll
        for (int r = 1; r <= 2; r <<= 1) {
            float Mo = __shfl_xor_sync(0xffffffffu, M, r);
            float So = __shfl_xor_sync(0xffffffffu, S, r);
            float Mn = fmaxf(M, Mo);
            float es = __expf(M  - Mn);
            float eo = __expf(Mo - Mn);
            S = S * es + So * eo;
            #pragma unroll
            for (int d = 0; d < ND; d++) {
                float ao = __shfl_xor_sync(0xffffffffu, acc[d], r);
                acc[d] = acc[d] * es + ao * eo;
            }
            M = Mn;
        }

        // ---- Euler-Maruyama update (replicated across the 4-thread group) ----
        float invS = 1.0f / S;
        const float4* np = reinterpret_cast<const float4*>(
            noise + ((size_t)i * NB + (size_t)sample) * ND);
        #pragma unroll
        for (int j = 0; j < 8; j++) {
            float4 z = np[j];
            int d = 4 * j;
            // score_d = -invS * acc[d];  0.5*x + score:
            float c0 = fmaf(-invS, acc[d+0], 0.5f * x[d+0]);
            float c1 = fmaf(-invS, acc[d+1], 0.5f * x[d+1]);
            float c2 = fmaf(-invS, acc[d+2], 0.5f * x[d+2]);
            float c3 = fmaf(-invS, acc[d+3], 0.5f * x[d+3]);
            x[d+0] = fmaf(sn, z.x, fmaf(hb, c0, x[d+0]));
            x[d+1] = fmaf(sn, z.y, fmaf(hb, c1, x[d+1]));
            x[d+2] = fmaf(sn, z.z, fmaf(hb, c2, x[d+2]));
            x[d+3] = fmaf(sn, z.w, fmaf(hb, c3, x[d+3]));
        }
    }

    // ---- write final x (one thread per sample) ----
    if (kpart == 0) {
        float4* op = reinterpret_cast<float4*>(out + (size_t)sample * ND);
        #pragma unroll
        for (int j = 0; j < 8; j++) {
            op[j] = make_float4(x[4*j+0], x[4*j+1], x[4*j+2], x[4*j+3]);
        }
    }
}

extern "C" void kernel_launch(void* const* d_in, const int* in_sizes, int n_in,
                              void* d_out, int out_size)
{
    const float* x_init  = (const float*)d_in[0];
    const float* centers = (const float*)d_in[1];
    const float* stds    = (const float*)d_in[2];
    const float* weights = (const float*)d_in[3];
    const float* noise   = (const float*)d_in[4];
    float* out = (float*)d_out;

    sbm_kernel<<<NB / SPB, TPB>>>(x_init, centers, stds, weights, noise, out);
}